// round 12
// baseline (speedup 1.0000x reference)
#include <cuda_runtime.h>
#include <cuda_bf16.h>
#include <cstdint>

// Problem constants (fixed by the reference)
#define NUM_USERS 100000
#define NUM_ITEMS 50000
#define N_NODES   150000   // NUM_USERS + NUM_ITEMS
#define DIM       128      // LATENT_DIM * K
#define DIM4      32       // DIM/4: float4 per row == uint2(4xbf16) per row
#define CAP       64       // per-row bucket capacity (max degree ~50)

// ---------------------------------------------------------------------------
// Scratch (__device__ globals per harness allocation rules).
// CRITICAL (R10 lesson): these symbols are ONLY dereferenced inside device
// code. Passing them as kernel arguments from host code yields the host
// shadow address, silently corrupting everything.
// ---------------------------------------------------------------------------
__device__ __nv_bfloat16  g_x0h[(size_t)N_NODES * DIM];  // bf16 gather sources
__device__ __nv_bfloat16  g_x1h[(size_t)N_NODES * DIM];
__device__ __nv_bfloat16  g_x2h[(size_t)N_NODES * DIM];
__device__ float          g_x1 [(size_t)N_NODES * DIM];  // f32, flagged rows only
__device__ float          g_x2 [(size_t)N_NODES * DIM];
__device__ int            g_cnt[N_NODES];
__device__ unsigned char  g_flag[N_NODES];
__device__ int2           g_bucket[(size_t)N_NODES * CAP];

// ---------------------------------------------------------------------------
// 1. zero per-row counters + batch flags
// ---------------------------------------------------------------------------
__global__ void zero_cnt_kernel() {
    int i = blockIdx.x * blockDim.x + threadIdx.x;
    int stride = gridDim.x * blockDim.x;
    for (; i < N_NODES; i += stride) { g_cnt[i] = 0; g_flag[i] = 0; }
}

// ---------------------------------------------------------------------------
// 2. pack inputs (virtual concat) to bf16 gather source g_x0h.
// ---------------------------------------------------------------------------
__global__ void pack_x0_kernel(const float* __restrict__ ue,
                               const float* __restrict__ ie) {
    int i = blockIdx.x * blockDim.x + threadIdx.x;
    int stride = gridDim.x * blockDim.x;
    const int total = N_NODES * DIM4;
    for (; i < total; i += stride) {
        int row = i >> 5;            // / DIM4
        int c   = i & 31;
        float4 a = (row < NUM_USERS)
                 ? __ldcs(reinterpret_cast<const float4*>(ue) + (size_t)row * DIM4 + c)
                 : __ldcs(reinterpret_cast<const float4*>(ie) + (size_t)(row - NUM_USERS) * DIM4 + c);
        __nv_bfloat162 h0 = __float22bfloat162_rn(make_float2(a.x, a.y));
        __nv_bfloat162 h1 = __float22bfloat162_rn(make_float2(a.z, a.w));
        uint2 r;
        r.x = *reinterpret_cast<unsigned int*>(&h0);
        r.y = *reinterpret_cast<unsigned int*>(&h1);
        reinterpret_cast<uint2*>(g_x0h)[i] = r;
    }
}

// ---------------------------------------------------------------------------
// 3. bucket scatter: one edge per thread; first 2*batch threads also set
//    batch flags. Bucket stores {src_offset_in_uint2, val_bits} so the
//    gather loop needs zero per-edge index math. Bucket fill order is
//    atomic-race dependent -> ~1e-7 rel fp-order noise downstream; benign.
// ---------------------------------------------------------------------------
__global__ void scatter_kernel(const int* __restrict__ src,
                               const int* __restrict__ dst,
                               const float* __restrict__ val,
                               const int* __restrict__ users,
                               const int* __restrict__ items,
                               int n_edges, int batch) {
    int i = blockIdx.x * blockDim.x + threadIdx.x;
    if (i < batch)               g_flag[users[i]] = 1;
    else if (i < 2 * batch)      g_flag[NUM_USERS + items[i - batch]] = 1;
    if (i >= n_edges) return;
    int d   = dst[i];
    int pos = atomicAdd(&g_cnt[d], 1);
    if (pos < CAP)  // never taken for this data; guards OOB
        g_bucket[(size_t)d * CAP + pos] = make_int2(src[i] * DIM4, __float_as_int(val[i]));
}

// ---------------------------------------------------------------------------
// bf16x4 (uint2) -> 4 fma into float4 acc. bf16->f32 expansion is EXACT bit
// surgery (shift / mask): alu-pipe rt-2 ops, no CVT slow path.
// bf16x2 word layout: .x in bits[15:0], .y in bits[31:16].
// ---------------------------------------------------------------------------
__device__ __forceinline__ void fma_bf16x4(float4& acc, float v, uint2 h) {
    float f0 = __int_as_float(h.x << 16);
    float f1 = __int_as_float(h.x & 0xFFFF0000u);
    float f2 = __int_as_float(h.y << 16);
    float f3 = __int_as_float(h.y & 0xFFFF0000u);
    acc.x = fmaf(v, f0, acc.x);
    acc.y = fmaf(v, f1, acc.y);
    acc.z = fmaf(v, f2, acc.z);
    acc.w = fmaf(v, f3, acc.w);
}

// Device-side buffer dispatch (compile-time): B = which bf16 layer to gather.
template <int B>
__device__ __forceinline__ const uint2* hsrc_ptr() {
    if (B == 0) return reinterpret_cast<const uint2*>(g_x0h);
    if (B == 1) return reinterpret_cast<const uint2*>(g_x1h);
    return reinterpret_cast<const uint2*>(g_x2h);
}

// ---------------------------------------------------------------------------
// Unified bf16 row gather: acc[lane] = sum_e val_e * xB[src_e][lane].
// Warp-collective; lane owns 4 consecutive bf16 (one uint2) of the row.
// 4-deep MLP batching (R5 lesson: occupancy > per-warp depth); __ldcg on
// gathers (~0% L1 hit -> skip the L1 allocate/fill path).
// ---------------------------------------------------------------------------
template <int B>
__device__ __forceinline__ float4 gather_row(int row, int lane) {
    const uint2* __restrict__ hsrc = hsrc_ptr<B>();
    const int deg = min(g_cnt[row], CAP);
    const int2* brow = g_bucket + (size_t)row * CAP;
    const int2 m0 = __ldcg(brow + lane);  // always in-bounds (CAP slots)

    float4 acc = make_float4(0.f, 0.f, 0.f, 0.f);
    const int n1 = min(deg, 32);

    int j = 0;
    for (; j + 4 <= n1; j += 4) {
        int o0 = __shfl_sync(0xffffffffu, m0.x, j);
        int o1 = __shfl_sync(0xffffffffu, m0.x, j + 1);
        int o2 = __shfl_sync(0xffffffffu, m0.x, j + 2);
        int o3 = __shfl_sync(0xffffffffu, m0.x, j + 3);
        float v0 = __int_as_float(__shfl_sync(0xffffffffu, m0.y, j));
        float v1 = __int_as_float(__shfl_sync(0xffffffffu, m0.y, j + 1));
        float v2 = __int_as_float(__shfl_sync(0xffffffffu, m0.y, j + 2));
        float v3 = __int_as_float(__shfl_sync(0xffffffffu, m0.y, j + 3));
        uint2 h0 = __ldcg(hsrc + o0 + lane);
        uint2 h1 = __ldcg(hsrc + o1 + lane);
        uint2 h2 = __ldcg(hsrc + o2 + lane);
        uint2 h3 = __ldcg(hsrc + o3 + lane);
        fma_bf16x4(acc, v0, h0); fma_bf16x4(acc, v1, h1);
        fma_bf16x4(acc, v2, h2); fma_bf16x4(acc, v3, h3);
    }
    for (; j < n1; j++) {
        int   oo = __shfl_sync(0xffffffffu, m0.x, j);
        float vv = __int_as_float(__shfl_sync(0xffffffffu, m0.y, j));
        fma_bf16x4(acc, vv, __ldcg(hsrc + oo + lane));
    }

    if (deg > 32) {  // rare tail (P(deg>32) ~ 0.4% of item rows)
        const int2 m1 = __ldcg(brow + 32 + lane);
        const int n2 = deg - 32;  // <= 32 since CAP = 64
        for (int t = 0; t < n2; t++) {
            int   oo = __shfl_sync(0xffffffffu, m1.x, t);
            float vv = __int_as_float(__shfl_sync(0xffffffffu, m1.y, t));
            fma_bf16x4(acc, vv, __ldcg(hsrc + oo + lane));
        }
    }
    return acc;
}

__device__ __forceinline__ uint2 pack_bf16x4(float4 a) {
    __nv_bfloat162 h0 = __float22bfloat162_rn(make_float2(a.x, a.y));
    __nv_bfloat162 h1 = __float22bfloat162_rn(make_float2(a.z, a.w));
    uint2 r;
    r.x = *reinterpret_cast<unsigned int*>(&h0);
    r.y = *reinterpret_cast<unsigned int*>(&h1);
    return r;
}

// ---------------------------------------------------------------------------
// 4/5. Pull-mode SpMM: one warp per destination row. LAYER selects both the
//      gather source (LAYER-1) and the output buffers — ALL via device-side
//      symbols. bf16 copy stored for every row (next stage's gather source);
//      f32 row stored only at flagged batch rows (the only f32 consumers).
// ---------------------------------------------------------------------------
template <int LAYER>
__global__ void __launch_bounds__(256, 7)
spmm_kernel() {
    const int warp = (blockIdx.x * blockDim.x + threadIdx.x) >> 5;
    const int lane = threadIdx.x & 31;
    if (warp >= N_NODES) return;

    float4 acc = gather_row<LAYER - 1>(warp, lane);

    float*         fdst = (LAYER == 1) ? g_x1 : g_x2;
    __nv_bfloat16* hb   = (LAYER == 1) ? g_x1h : g_x2h;

    reinterpret_cast<uint2*>(hb)[(size_t)warp * DIM4 + lane] = pack_bf16x4(acc);
    if (g_flag[warp])  // warp-uniform; only batch rows need f32 precision
        __stcs(reinterpret_cast<float4*>(fdst) + (size_t)warp * DIM4 + lane, acc);
}

// ---------------------------------------------------------------------------
// 6. Fused layer-3 + mean + dot. One warp per batch element; x3 rows are
//    computed on the fly from the bf16 x2 copy. Direct terms read f32.
//    out = dot(x0u+x1u+x2u+x3u, x0i+x1i+x2i+x3i) / 16
// ---------------------------------------------------------------------------
__global__ void __launch_bounds__(256)
dot_fused_kernel(const float* __restrict__ ue, const float* __restrict__ ie,
                 const int* __restrict__ users, const int* __restrict__ items,
                 float* __restrict__ out, int batch) {
    const int warp = (blockIdx.x * blockDim.x + threadIdx.x) >> 5;
    const int lane = threadIdx.x & 31;
    if (warp >= batch) return;

    const int u   = users[warp];
    const int it  = items[warp];
    const int itn = NUM_USERS + it;

    float4 a3 = gather_row<2>(u,   lane);
    float4 b3 = gather_row<2>(itn, lane);

    const size_t ru = (size_t)u * DIM4;
    const size_t ri = (size_t)itn * DIM4;
    float4 a0 = __ldg(reinterpret_cast<const float4*>(ue) + (size_t)u * DIM4 + lane);
    float4 a1 = __ldg(reinterpret_cast<const float4*>(g_x1) + ru + lane);
    float4 a2 = __ldg(reinterpret_cast<const float4*>(g_x2) + ru + lane);
    float4 b0 = __ldg(reinterpret_cast<const float4*>(ie) + (size_t)it * DIM4 + lane);
    float4 b1 = __ldg(reinterpret_cast<const float4*>(g_x1) + ri + lane);
    float4 b2 = __ldg(reinterpret_cast<const float4*>(g_x2) + ri + lane);

    float sux = a0.x + a1.x + a2.x + a3.x;
    float suy = a0.y + a1.y + a2.y + a3.y;
    float suz = a0.z + a1.z + a2.z + a3.z;
    float suw = a0.w + a1.w + a2.w + a3.w;

    float six = b0.x + b1.x + b2.x + b3.x;
    float siy = b0.y + b1.y + b2.y + b3.y;
    float siz = b0.z + b1.z + b2.z + b3.z;
    float siw = b0.w + b1.w + b2.w + b3.w;

    float p = sux * six + suy * siy + suz * siz + suw * siw;

    #pragma unroll
    for (int off = 16; off > 0; off >>= 1)
        p += __shfl_xor_sync(0xffffffffu, p, off);

    if (lane == 0) out[warp] = p * 0.0625f;  // mean /4 each side -> /16
}

// ---------------------------------------------------------------------------
extern "C" void kernel_launch(void* const* d_in, const int* in_sizes, int n_in,
                              void* d_out, int out_size) {
    const float* user_emb = (const float*)d_in[0];
    const float* item_emb = (const float*)d_in[1];
    const int*   src      = (const int*)  d_in[2];
    const int*   dst      = (const int*)  d_in[3];
    const float* val      = (const float*)d_in[4];
    const int*   users    = (const int*)  d_in[5];
    const int*   items    = (const int*)  d_in[6];
    float*       out      = (float*)d_out;

    const int n_edges = in_sizes[2];
    const int batch   = in_sizes[5];

    // counters+flags, bf16 input pack, bucket build (scatter also sets flags)
    zero_cnt_kernel<<<148, 1024>>>();
    pack_x0_kernel<<<1480, 256>>>(user_emb, item_emb);
    scatter_kernel<<<(n_edges + 255) / 256, 256>>>(src, dst, val,
                                                   users, items, n_edges, batch);

    // Two pull-mode SpMM layers (one warp per dst row), unified bf16 gathers.
    // NOTE: no scratch-buffer pointers cross the host/device boundary.
    const int spmm_blocks = (N_NODES * 32 + 255) / 256;
    spmm_kernel<1><<<spmm_blocks, 256>>>();
    spmm_kernel<2><<<spmm_blocks, 256>>>();

    // Fused layer-3 + mean + dot (one warp per batch element).
    dot_fused_kernel<<<(batch * 32 + 255) / 256, 256>>>(user_emb, item_emb,
                                                        users, items, out, batch);
}

// round 13
// speedup vs baseline: 1.0425x; 1.0425x over previous
#include <cuda_runtime.h>
#include <cuda_bf16.h>
#include <cstdint>

// Problem constants (fixed by the reference)
#define NUM_USERS 100000
#define NUM_ITEMS 50000
#define N_NODES   150000   // NUM_USERS + NUM_ITEMS
#define DIM       128      // LATENT_DIM * K
#define DIM4      32       // DIM/4: float4 per row == uint2(4xbf16) per row
#define UOFF      (NUM_USERS * DIM4)  // user/item split in row-offset units
#define CAP       64       // per-row bucket capacity (max degree ~50)

// ---------------------------------------------------------------------------
// Scratch (__device__ globals per harness allocation rules).
// CRITICAL (R10 lesson): these symbols are ONLY dereferenced inside device
// code — never passed as kernel arguments from host code (host shadow addr).
// ---------------------------------------------------------------------------
__device__ __nv_bfloat16  g_x1h[(size_t)N_NODES * DIM];  // bf16 gather sources
__device__ __nv_bfloat16  g_x2h[(size_t)N_NODES * DIM];
__device__ float          g_x1 [(size_t)N_NODES * DIM];  // f32, flagged rows only
__device__ float          g_x2 [(size_t)N_NODES * DIM];
__device__ int            g_cnt[N_NODES];
__device__ unsigned char  g_flag[N_NODES];
__device__ int2           g_bucket[(size_t)N_NODES * CAP];

// ---------------------------------------------------------------------------
// 1. zero per-row counters + batch flags
// ---------------------------------------------------------------------------
__global__ void zero_cnt_kernel() {
    int i = blockIdx.x * blockDim.x + threadIdx.x;
    int stride = gridDim.x * blockDim.x;
    for (; i < N_NODES; i += stride) { g_cnt[i] = 0; g_flag[i] = 0; }
}

// ---------------------------------------------------------------------------
// 2. bucket scatter: one edge per thread; first 2*batch threads also set
//    batch flags. Bucket stores {src_row_offset (x DIM4), val_bits}: zero
//    per-edge index math in the gather loops. Fill order is atomic-race
//    dependent -> ~1e-7 rel fp-order noise downstream; benign.
// ---------------------------------------------------------------------------
__global__ void scatter_kernel(const int* __restrict__ src,
                               const int* __restrict__ dst,
                               const float* __restrict__ val,
                               const int* __restrict__ users,
                               const int* __restrict__ items,
                               int n_edges, int batch) {
    int i = blockIdx.x * blockDim.x + threadIdx.x;
    if (i < batch)               g_flag[users[i]] = 1;
    else if (i < 2 * batch)      g_flag[NUM_USERS + items[i - batch]] = 1;
    if (i >= n_edges) return;
    int d   = dst[i];
    int pos = atomicAdd(&g_cnt[d], 1);
    if (pos < CAP)  // never taken for this data; guards OOB
        g_bucket[(size_t)d * CAP + pos] = make_int2(src[i] * DIM4, __float_as_int(val[i]));
}

// ---------------------------------------------------------------------------
// Packed helpers. bf16->f32 expansion is exact bit surgery; the two expanded
// values are paired into a 64-bit reg and consumed by fma.rn.f32x2 (FFMA2) —
// the ptxas-absent pattern that halves FFMA count on the issue-bound kernel.
// ---------------------------------------------------------------------------
__device__ __forceinline__ void fma_bf16x4_packed(unsigned long long& acc01,
                                                  unsigned long long& acc23,
                                                  unsigned long long vv2,
                                                  uint2 h) {
    unsigned int f0 = h.x << 16;
    unsigned int f1 = h.x & 0xFFFF0000u;
    unsigned int f2 = h.y << 16;
    unsigned int f3 = h.y & 0xFFFF0000u;
    unsigned long long p01, p23;
    asm("mov.b64 %0, {%1, %2};" : "=l"(p01) : "r"(f0), "r"(f1));
    asm("mov.b64 %0, {%1, %2};" : "=l"(p23) : "r"(f2), "r"(f3));
    asm("fma.rn.f32x2 %0, %1, %2, %0;" : "+l"(acc01) : "l"(p01), "l"(vv2));
    asm("fma.rn.f32x2 %0, %1, %2, %0;" : "+l"(acc23) : "l"(p23), "l"(vv2));
}

__device__ __forceinline__ unsigned long long pack_vv2(int vbits) {
    unsigned long long r;
    asm("mov.b64 %0, {%1, %1};" : "=l"(r) : "r"(vbits));
    return r;
}

// Device-side bf16 buffer dispatch (compile-time).
template <int B>
__device__ __forceinline__ const uint2* hsrc_ptr() {
    return reinterpret_cast<const uint2*>((B == 1) ? g_x1h : g_x2h);
}

// ---------------------------------------------------------------------------
// bf16 row gather (layers 2/3): acc[lane] = sum_e val_e * xB[src_e][lane].
// Warp-collective; lane owns 4 consecutive bf16 (one uint2) of the row.
// 4-deep MLP batching (R5: occupancy > per-warp depth); __ldcg (~0% L1 hit).
// ---------------------------------------------------------------------------
template <int B>
__device__ __forceinline__ float4 gather_row_h(int row, int lane) {
    const uint2* __restrict__ hsrc = hsrc_ptr<B>();
    const int deg = min(g_cnt[row], CAP);
    const int2* brow = g_bucket + (size_t)row * CAP;
    const int2 m0 = __ldcg(brow + lane);  // always in-bounds (CAP slots)

    unsigned long long acc01 = 0ull, acc23 = 0ull;
    const int n1 = min(deg, 32);

    int j = 0;
    for (; j + 4 <= n1; j += 4) {
        int o0 = __shfl_sync(0xffffffffu, m0.x, j);
        int o1 = __shfl_sync(0xffffffffu, m0.x, j + 1);
        int o2 = __shfl_sync(0xffffffffu, m0.x, j + 2);
        int o3 = __shfl_sync(0xffffffffu, m0.x, j + 3);
        unsigned long long v0 = pack_vv2(__shfl_sync(0xffffffffu, m0.y, j));
        unsigned long long v1 = pack_vv2(__shfl_sync(0xffffffffu, m0.y, j + 1));
        unsigned long long v2 = pack_vv2(__shfl_sync(0xffffffffu, m0.y, j + 2));
        unsigned long long v3 = pack_vv2(__shfl_sync(0xffffffffu, m0.y, j + 3));
        uint2 h0 = __ldcg(hsrc + o0 + lane);
        uint2 h1 = __ldcg(hsrc + o1 + lane);
        uint2 h2 = __ldcg(hsrc + o2 + lane);
        uint2 h3 = __ldcg(hsrc + o3 + lane);
        fma_bf16x4_packed(acc01, acc23, v0, h0);
        fma_bf16x4_packed(acc01, acc23, v1, h1);
        fma_bf16x4_packed(acc01, acc23, v2, h2);
        fma_bf16x4_packed(acc01, acc23, v3, h3);
    }
    for (; j < n1; j++) {
        int oo = __shfl_sync(0xffffffffu, m0.x, j);
        unsigned long long vv = pack_vv2(__shfl_sync(0xffffffffu, m0.y, j));
        fma_bf16x4_packed(acc01, acc23, vv, __ldcg(hsrc + oo + lane));
    }

    if (deg > 32) {  // rare tail (P(deg>32) ~ 0.4% of item rows)
        const int2 m1 = __ldcg(brow + 32 + lane);
        const int n2 = deg - 32;  // <= 32 since CAP = 64
        for (int t = 0; t < n2; t++) {
            int oo = __shfl_sync(0xffffffffu, m1.x, t);
            unsigned long long vv = pack_vv2(__shfl_sync(0xffffffffu, m1.y, t));
            fma_bf16x4_packed(acc01, acc23, vv, __ldcg(hsrc + oo + lane));
        }
    }

    float4 r;
    asm("mov.b64 {%0, %1}, %2;" : "=f"(r.x), "=f"(r.y) : "l"(acc01));
    asm("mov.b64 {%0, %1}, %2;" : "=f"(r.z), "=f"(r.w) : "l"(acc23));
    return r;
}

// ---------------------------------------------------------------------------
// f32 row gather (layer 1): reads the harness input embeddings directly
// (virtual concat). f32 here is precision-load-bearing: quantizing x0 was
// measured (R11) to cost +5.5e-4 rel_err — rejected.
// ---------------------------------------------------------------------------
__device__ __forceinline__ float4 gather_row_f32(const float4* __restrict__ ue4,
                                                 const float4* __restrict__ ie4,
                                                 int row, int lane) {
    const int deg = min(g_cnt[row], CAP);
    const int2* brow = g_bucket + (size_t)row * CAP;
    const int2 m0 = __ldcg(brow + lane);

    float4 acc = make_float4(0.f, 0.f, 0.f, 0.f);
    const int n1 = min(deg, 32);

    int j = 0;
    for (; j + 4 <= n1; j += 4) {
        int o0 = __shfl_sync(0xffffffffu, m0.x, j);
        int o1 = __shfl_sync(0xffffffffu, m0.x, j + 1);
        int o2 = __shfl_sync(0xffffffffu, m0.x, j + 2);
        int o3 = __shfl_sync(0xffffffffu, m0.x, j + 3);
        float v0 = __int_as_float(__shfl_sync(0xffffffffu, m0.y, j));
        float v1 = __int_as_float(__shfl_sync(0xffffffffu, m0.y, j + 1));
        float v2 = __int_as_float(__shfl_sync(0xffffffffu, m0.y, j + 2));
        float v3 = __int_as_float(__shfl_sync(0xffffffffu, m0.y, j + 3));
        float4 a = __ldcg(((o0 < UOFF) ? ue4 + o0 : ie4 + (o0 - UOFF)) + lane);
        float4 b = __ldcg(((o1 < UOFF) ? ue4 + o1 : ie4 + (o1 - UOFF)) + lane);
        float4 c = __ldcg(((o2 < UOFF) ? ue4 + o2 : ie4 + (o2 - UOFF)) + lane);
        float4 d = __ldcg(((o3 < UOFF) ? ue4 + o3 : ie4 + (o3 - UOFF)) + lane);
        acc.x = fmaf(v0, a.x, acc.x); acc.y = fmaf(v0, a.y, acc.y);
        acc.z = fmaf(v0, a.z, acc.z); acc.w = fmaf(v0, a.w, acc.w);
        acc.x = fmaf(v1, b.x, acc.x); acc.y = fmaf(v1, b.y, acc.y);
        acc.z = fmaf(v1, b.z, acc.z); acc.w = fmaf(v1, b.w, acc.w);
        acc.x = fmaf(v2, c.x, acc.x); acc.y = fmaf(v2, c.y, acc.y);
        acc.z = fmaf(v2, c.z, acc.z); acc.w = fmaf(v2, c.w, acc.w);
        acc.x = fmaf(v3, d.x, acc.x); acc.y = fmaf(v3, d.y, acc.y);
        acc.z = fmaf(v3, d.z, acc.z); acc.w = fmaf(v3, d.w, acc.w);
    }
    for (; j < n1; j++) {
        int   oo = __shfl_sync(0xffffffffu, m0.x, j);
        float vv = __int_as_float(__shfl_sync(0xffffffffu, m0.y, j));
        float4 m = __ldcg(((oo < UOFF) ? ue4 + oo : ie4 + (oo - UOFF)) + lane);
        acc.x = fmaf(vv, m.x, acc.x); acc.y = fmaf(vv, m.y, acc.y);
        acc.z = fmaf(vv, m.z, acc.z); acc.w = fmaf(vv, m.w, acc.w);
    }

    if (deg > 32) {
        const int2 m1 = __ldcg(brow + 32 + lane);
        const int n2 = deg - 32;
        for (int t = 0; t < n2; t++) {
            int   oo = __shfl_sync(0xffffffffu, m1.x, t);
            float vv = __int_as_float(__shfl_sync(0xffffffffu, m1.y, t));
            float4 m = __ldcg(((oo < UOFF) ? ue4 + oo : ie4 + (oo - UOFF)) + lane);
            acc.x = fmaf(vv, m.x, acc.x); acc.y = fmaf(vv, m.y, acc.y);
            acc.z = fmaf(vv, m.z, acc.z); acc.w = fmaf(vv, m.w, acc.w);
        }
    }
    return acc;
}

__device__ __forceinline__ uint2 pack_bf16x4(float4 a) {
    __nv_bfloat162 h0 = __float22bfloat162_rn(make_float2(a.x, a.y));
    __nv_bfloat162 h1 = __float22bfloat162_rn(make_float2(a.z, a.w));
    uint2 r;
    r.x = *reinterpret_cast<unsigned int*>(&h0);
    r.y = *reinterpret_cast<unsigned int*>(&h1);
    return r;
}

// ---------------------------------------------------------------------------
// 3. SpMM layer 1: f32 gathers from inputs -> x1 (bf16 copy for all rows;
//    f32 only at flagged batch rows — the only f32 consumers).
// ---------------------------------------------------------------------------
__global__ void __launch_bounds__(256, 7)
spmm1_kernel(const float* __restrict__ ue, const float* __restrict__ ie) {
    const int warp = (blockIdx.x * blockDim.x + threadIdx.x) >> 5;
    const int lane = threadIdx.x & 31;
    if (warp >= N_NODES) return;

    float4 acc = gather_row_f32(reinterpret_cast<const float4*>(ue),
                                reinterpret_cast<const float4*>(ie), warp, lane);

    reinterpret_cast<uint2*>(g_x1h)[(size_t)warp * DIM4 + lane] = pack_bf16x4(acc);
    if (g_flag[warp])  // warp-uniform
        __stcs(reinterpret_cast<float4*>(g_x1) + (size_t)warp * DIM4 + lane, acc);
}

// ---------------------------------------------------------------------------
// 4. SpMM layer 2: bf16 gathers from x1h -> x2 (same dual-store scheme).
// ---------------------------------------------------------------------------
__global__ void __launch_bounds__(256, 7)
spmm2_kernel() {
    const int warp = (blockIdx.x * blockDim.x + threadIdx.x) >> 5;
    const int lane = threadIdx.x & 31;
    if (warp >= N_NODES) return;

    float4 acc = gather_row_h<1>(warp, lane);

    reinterpret_cast<uint2*>(g_x2h)[(size_t)warp * DIM4 + lane] = pack_bf16x4(acc);
    if (g_flag[warp])
        __stcs(reinterpret_cast<float4*>(g_x2) + (size_t)warp * DIM4 + lane, acc);
}

// ---------------------------------------------------------------------------
// 5. Fused layer-3 + mean + dot. One warp per batch element; x3 rows are
//    computed on the fly from the bf16 x2 copy. Direct terms read f32.
//    out = dot(x0u+x1u+x2u+x3u, x0i+x1i+x2i+x3i) / 16
// ---------------------------------------------------------------------------
__global__ void __launch_bounds__(256)
dot_fused_kernel(const float* __restrict__ ue, const float* __restrict__ ie,
                 const int* __restrict__ users, const int* __restrict__ items,
                 float* __restrict__ out, int batch) {
    const int warp = (blockIdx.x * blockDim.x + threadIdx.x) >> 5;
    const int lane = threadIdx.x & 31;
    if (warp >= batch) return;

    const int u   = users[warp];
    const int it  = items[warp];
    const int itn = NUM_USERS + it;

    float4 a3 = gather_row_h<2>(u,   lane);
    float4 b3 = gather_row_h<2>(itn, lane);

    const size_t ru = (size_t)u * DIM4;
    const size_t ri = (size_t)itn * DIM4;
    float4 a0 = __ldg(reinterpret_cast<const float4*>(ue) + (size_t)u * DIM4 + lane);
    float4 a1 = __ldg(reinterpret_cast<const float4*>(g_x1) + ru + lane);
    float4 a2 = __ldg(reinterpret_cast<const float4*>(g_x2) + ru + lane);
    float4 b0 = __ldg(reinterpret_cast<const float4*>(ie) + (size_t)it * DIM4 + lane);
    float4 b1 = __ldg(reinterpret_cast<const float4*>(g_x1) + ri + lane);
    float4 b2 = __ldg(reinterpret_cast<const float4*>(g_x2) + ri + lane);

    float sux = a0.x + a1.x + a2.x + a3.x;
    float suy = a0.y + a1.y + a2.y + a3.y;
    float suz = a0.z + a1.z + a2.z + a3.z;
    float suw = a0.w + a1.w + a2.w + a3.w;

    float six = b0.x + b1.x + b2.x + b3.x;
    float siy = b0.y + b1.y + b2.y + b3.y;
    float siz = b0.z + b1.z + b2.z + b3.z;
    float siw = b0.w + b1.w + b2.w + b3.w;

    float p = sux * six + suy * siy + suz * siz + suw * siw;

    #pragma unroll
    for (int off = 16; off > 0; off >>= 1)
        p += __shfl_xor_sync(0xffffffffu, p, off);

    if (lane == 0) out[warp] = p * 0.0625f;  // mean /4 each side -> /16
}

// ---------------------------------------------------------------------------
extern "C" void kernel_launch(void* const* d_in, const int* in_sizes, int n_in,
                              void* d_out, int out_size) {
    const float* user_emb = (const float*)d_in[0];
    const float* item_emb = (const float*)d_in[1];
    const int*   src      = (const int*)  d_in[2];
    const int*   dst      = (const int*)  d_in[3];
    const float* val      = (const float*)d_in[4];
    const int*   users    = (const int*)  d_in[5];
    const int*   items    = (const int*)  d_in[6];
    float*       out      = (float*)d_out;

    const int n_edges = in_sizes[2];
    const int batch   = in_sizes[5];

    // counters+flags, bucket build (scatter also sets batch flags)
    zero_cnt_kernel<<<148, 1024>>>();
    scatter_kernel<<<(n_edges + 255) / 256, 256>>>(src, dst, val,
                                                   users, items, n_edges, batch);

    // Two pull-mode SpMM layers (one warp per dst row).
    const int spmm_blocks = (N_NODES * 32 + 255) / 256;
    spmm1_kernel<<<spmm_blocks, 256>>>(user_emb, item_emb);
    spmm2_kernel<<<spmm_blocks, 256>>>();

    // Fused layer-3 + mean + dot (one warp per batch element).
    dot_fused_kernel<<<(batch * 32 + 255) / 256, 256>>>(user_emb, item_emb,
                                                        users, items, out, batch);
}

// round 14
// speedup vs baseline: 1.0523x; 1.0093x over previous
#include <cuda_runtime.h>
#include <cuda_bf16.h>
#include <cstdint>

// Problem constants (fixed by the reference)
#define NUM_USERS 100000
#define NUM_ITEMS 50000
#define N_NODES   150000   // NUM_USERS + NUM_ITEMS
#define DIM       128      // LATENT_DIM * K
#define DIM4      32       // DIM/4: float4 per row == uint2(4xbf16) per row
#define UOFF      (NUM_USERS * DIM4)  // user/item split in row-offset units
#define CAP       64       // per-row bucket capacity (max degree ~50)

// ---------------------------------------------------------------------------
// Scratch (__device__ globals per harness allocation rules).
// CRITICAL (R10 lesson): these symbols are ONLY dereferenced inside device
// code — never passed as kernel arguments from host code (host shadow addr).
// ---------------------------------------------------------------------------
__device__ __nv_bfloat16  g_x1h[(size_t)N_NODES * DIM];  // bf16 gather sources
__device__ __nv_bfloat16  g_x2h[(size_t)N_NODES * DIM];
__device__ float          g_x1 [(size_t)N_NODES * DIM];  // f32, flagged rows only
__device__ float          g_x2 [(size_t)N_NODES * DIM];
__device__ int            g_cnt[N_NODES];
__device__ unsigned char  g_flag[N_NODES];
__device__ int2           g_bucket[(size_t)N_NODES * CAP];

// ---------------------------------------------------------------------------
// 1. zero per-row counters + batch flags
// ---------------------------------------------------------------------------
__global__ void zero_cnt_kernel() {
    int i = blockIdx.x * blockDim.x + threadIdx.x;
    int stride = gridDim.x * blockDim.x;
    for (; i < N_NODES; i += stride) { g_cnt[i] = 0; g_flag[i] = 0; }
}

// ---------------------------------------------------------------------------
// 2. bucket scatter: one edge per thread; first 2*batch threads also set
//    batch flags. Bucket stores {src_row_offset (x DIM4), val_bits}: zero
//    per-edge index math in the gather loops. Fill order is atomic-race
//    dependent -> ~1e-7 rel fp-order noise downstream; benign.
// ---------------------------------------------------------------------------
__global__ void scatter_kernel(const int* __restrict__ src,
                               const int* __restrict__ dst,
                               const float* __restrict__ val,
                               const int* __restrict__ users,
                               const int* __restrict__ items,
                               int n_edges, int batch) {
    int i = blockIdx.x * blockDim.x + threadIdx.x;
    if (i < batch)               g_flag[users[i]] = 1;
    else if (i < 2 * batch)      g_flag[NUM_USERS + items[i - batch]] = 1;
    if (i >= n_edges) return;
    int d   = dst[i];
    int pos = atomicAdd(&g_cnt[d], 1);
    if (pos < CAP)  // never taken for this data; guards OOB
        g_bucket[(size_t)d * CAP + pos] = make_int2(src[i] * DIM4, __float_as_int(val[i]));
}

// ---------------------------------------------------------------------------
// bf16x4 (uint2) -> 4 fmaf into float4 acc. bf16->f32 expansion is EXACT bit
// surgery (shift / mask): alu-pipe rt-2 ops, no CVT slow path, and — the R12
// lesson — no forced 64-bit register pairing (FFMA2 materialized real MOVs
// and regressed spmm2 63.9 -> 68.8 us; reverted).
// ---------------------------------------------------------------------------
__device__ __forceinline__ void fma_bf16x4(float4& acc, float v, uint2 h) {
    float f0 = __int_as_float(h.x << 16);
    float f1 = __int_as_float(h.x & 0xFFFF0000u);
    float f2 = __int_as_float(h.y << 16);
    float f3 = __int_as_float(h.y & 0xFFFF0000u);
    acc.x = fmaf(v, f0, acc.x);
    acc.y = fmaf(v, f1, acc.y);
    acc.z = fmaf(v, f2, acc.z);
    acc.w = fmaf(v, f3, acc.w);
}

// Device-side bf16 buffer dispatch (compile-time).
template <int B>
__device__ __forceinline__ const uint2* hsrc_ptr() {
    return reinterpret_cast<const uint2*>((B == 1) ? g_x1h : g_x2h);
}

// ---------------------------------------------------------------------------
// bf16 row gather (layers 2/3): acc[lane] = sum_e val_e * xB[src_e][lane].
// Warp-collective; lane owns 4 consecutive bf16 (one uint2) of the row.
// 4-deep MLP batching (R5: occupancy > per-warp depth); __ldcg (~0% L1 hit).
// ---------------------------------------------------------------------------
template <int B>
__device__ __forceinline__ float4 gather_row_h(int row, int lane) {
    const uint2* __restrict__ hsrc = hsrc_ptr<B>();
    const int deg = min(g_cnt[row], CAP);
    const int2* brow = g_bucket + (size_t)row * CAP;
    const int2 m0 = __ldcg(brow + lane);  // always in-bounds (CAP slots)

    float4 acc = make_float4(0.f, 0.f, 0.f, 0.f);
    const int n1 = min(deg, 32);

    int j = 0;
    for (; j + 4 <= n1; j += 4) {
        int o0 = __shfl_sync(0xffffffffu, m0.x, j);
        int o1 = __shfl_sync(0xffffffffu, m0.x, j + 1);
        int o2 = __shfl_sync(0xffffffffu, m0.x, j + 2);
        int o3 = __shfl_sync(0xffffffffu, m0.x, j + 3);
        float v0 = __int_as_float(__shfl_sync(0xffffffffu, m0.y, j));
        float v1 = __int_as_float(__shfl_sync(0xffffffffu, m0.y, j + 1));
        float v2 = __int_as_float(__shfl_sync(0xffffffffu, m0.y, j + 2));
        float v3 = __int_as_float(__shfl_sync(0xffffffffu, m0.y, j + 3));
        uint2 h0 = __ldcg(hsrc + o0 + lane);
        uint2 h1 = __ldcg(hsrc + o1 + lane);
        uint2 h2 = __ldcg(hsrc + o2 + lane);
        uint2 h3 = __ldcg(hsrc + o3 + lane);
        fma_bf16x4(acc, v0, h0); fma_bf16x4(acc, v1, h1);
        fma_bf16x4(acc, v2, h2); fma_bf16x4(acc, v3, h3);
    }
    for (; j < n1; j++) {
        int   oo = __shfl_sync(0xffffffffu, m0.x, j);
        float vv = __int_as_float(__shfl_sync(0xffffffffu, m0.y, j));
        fma_bf16x4(acc, vv, __ldcg(hsrc + oo + lane));
    }

    if (deg > 32) {  // rare tail (P(deg>32) ~ 0.4% of item rows)
        const int2 m1 = __ldcg(brow + 32 + lane);
        const int n2 = deg - 32;  // <= 32 since CAP = 64
        for (int t = 0; t < n2; t++) {
            int   oo = __shfl_sync(0xffffffffu, m1.x, t);
            float vv = __int_as_float(__shfl_sync(0xffffffffu, m1.y, t));
            fma_bf16x4(acc, vv, __ldcg(hsrc + oo + lane));
        }
    }
    return acc;
}

// ---------------------------------------------------------------------------
// f32 row gather (layer 1): reads the harness input embeddings directly
// (virtual concat). f32 here is precision-load-bearing: quantizing x0 was
// measured (R11) to cost +5.5e-4 rel_err — rejected.
// ---------------------------------------------------------------------------
__device__ __forceinline__ float4 gather_row_f32(const float4* __restrict__ ue4,
                                                 const float4* __restrict__ ie4,
                                                 int row, int lane) {
    const int deg = min(g_cnt[row], CAP);
    const int2* brow = g_bucket + (size_t)row * CAP;
    const int2 m0 = __ldcg(brow + lane);

    float4 acc = make_float4(0.f, 0.f, 0.f, 0.f);
    const int n1 = min(deg, 32);

    int j = 0;
    for (; j + 4 <= n1; j += 4) {
        int o0 = __shfl_sync(0xffffffffu, m0.x, j);
        int o1 = __shfl_sync(0xffffffffu, m0.x, j + 1);
        int o2 = __shfl_sync(0xffffffffu, m0.x, j + 2);
        int o3 = __shfl_sync(0xffffffffu, m0.x, j + 3);
        float v0 = __int_as_float(__shfl_sync(0xffffffffu, m0.y, j));
        float v1 = __int_as_float(__shfl_sync(0xffffffffu, m0.y, j + 1));
        float v2 = __int_as_float(__shfl_sync(0xffffffffu, m0.y, j + 2));
        float v3 = __int_as_float(__shfl_sync(0xffffffffu, m0.y, j + 3));
        float4 a = __ldcg(((o0 < UOFF) ? ue4 + o0 : ie4 + (o0 - UOFF)) + lane);
        float4 b = __ldcg(((o1 < UOFF) ? ue4 + o1 : ie4 + (o1 - UOFF)) + lane);
        float4 c = __ldcg(((o2 < UOFF) ? ue4 + o2 : ie4 + (o2 - UOFF)) + lane);
        float4 d = __ldcg(((o3 < UOFF) ? ue4 + o3 : ie4 + (o3 - UOFF)) + lane);
        acc.x = fmaf(v0, a.x, acc.x); acc.y = fmaf(v0, a.y, acc.y);
        acc.z = fmaf(v0, a.z, acc.z); acc.w = fmaf(v0, a.w, acc.w);
        acc.x = fmaf(v1, b.x, acc.x); acc.y = fmaf(v1, b.y, acc.y);
        acc.z = fmaf(v1, b.z, acc.z); acc.w = fmaf(v1, b.w, acc.w);
        acc.x = fmaf(v2, c.x, acc.x); acc.y = fmaf(v2, c.y, acc.y);
        acc.z = fmaf(v2, c.z, acc.z); acc.w = fmaf(v2, c.w, acc.w);
        acc.x = fmaf(v3, d.x, acc.x); acc.y = fmaf(v3, d.y, acc.y);
        acc.z = fmaf(v3, d.z, acc.z); acc.w = fmaf(v3, d.w, acc.w);
    }
    for (; j < n1; j++) {
        int   oo = __shfl_sync(0xffffffffu, m0.x, j);
        float vv = __int_as_float(__shfl_sync(0xffffffffu, m0.y, j));
        float4 m = __ldcg(((oo < UOFF) ? ue4 + oo : ie4 + (oo - UOFF)) + lane);
        acc.x = fmaf(vv, m.x, acc.x); acc.y = fmaf(vv, m.y, acc.y);
        acc.z = fmaf(vv, m.z, acc.z); acc.w = fmaf(vv, m.w, acc.w);
    }

    if (deg > 32) {
        const int2 m1 = __ldcg(brow + 32 + lane);
        const int n2 = deg - 32;
        for (int t = 0; t < n2; t++) {
            int   oo = __shfl_sync(0xffffffffu, m1.x, t);
            float vv = __int_as_float(__shfl_sync(0xffffffffu, m1.y, t));
            float4 m = __ldcg(((oo < UOFF) ? ue4 + oo : ie4 + (oo - UOFF)) + lane);
            acc.x = fmaf(vv, m.x, acc.x); acc.y = fmaf(vv, m.y, acc.y);
            acc.z = fmaf(vv, m.z, acc.z); acc.w = fmaf(vv, m.w, acc.w);
        }
    }
    return acc;
}

__device__ __forceinline__ uint2 pack_bf16x4(float4 a) {
    __nv_bfloat162 h0 = __float22bfloat162_rn(make_float2(a.x, a.y));
    __nv_bfloat162 h1 = __float22bfloat162_rn(make_float2(a.z, a.w));
    uint2 r;
    r.x = *reinterpret_cast<unsigned int*>(&h0);
    r.y = *reinterpret_cast<unsigned int*>(&h1);
    return r;
}

// ---------------------------------------------------------------------------
// 3. SpMM layer 1: f32 gathers from inputs -> x1 (bf16 copy for all rows;
//    f32 only at flagged batch rows — the only f32 consumers).
//    launch_bounds (256, 8): 32 regs x 2048 thr = full RF -> 100% occ target.
// ---------------------------------------------------------------------------
__global__ void __launch_bounds__(256, 8)
spmm1_kernel(const float* __restrict__ ue, const float* __restrict__ ie) {
    const int warp = (blockIdx.x * blockDim.x + threadIdx.x) >> 5;
    const int lane = threadIdx.x & 31;
    if (warp >= N_NODES) return;

    float4 acc = gather_row_f32(reinterpret_cast<const float4*>(ue),
                                reinterpret_cast<const float4*>(ie), warp, lane);

    reinterpret_cast<uint2*>(g_x1h)[(size_t)warp * DIM4 + lane] = pack_bf16x4(acc);
    if (g_flag[warp])  // warp-uniform
        __stcs(reinterpret_cast<float4*>(g_x1) + (size_t)warp * DIM4 + lane, acc);
}

// ---------------------------------------------------------------------------
// 4. SpMM layer 2: bf16 gathers from x1h -> x2 (same dual-store scheme).
// ---------------------------------------------------------------------------
__global__ void __launch_bounds__(256, 8)
spmm2_kernel() {
    const int warp = (blockIdx.x * blockDim.x + threadIdx.x) >> 5;
    const int lane = threadIdx.x & 31;
    if (warp >= N_NODES) return;

    float4 acc = gather_row_h<1>(warp, lane);

    reinterpret_cast<uint2*>(g_x2h)[(size_t)warp * DIM4 + lane] = pack_bf16x4(acc);
    if (g_flag[warp])
        __stcs(reinterpret_cast<float4*>(g_x2) + (size_t)warp * DIM4 + lane, acc);
}

// ---------------------------------------------------------------------------
// 5. Fused layer-3 + mean + dot. One warp per batch element; x3 rows are
//    computed on the fly from the bf16 x2 copy. Direct terms read f32.
//    out = dot(x0u+x1u+x2u+x3u, x0i+x1i+x2i+x3i) / 16
// ---------------------------------------------------------------------------
__global__ void __launch_bounds__(256)
dot_fused_kernel(const float* __restrict__ ue, const float* __restrict__ ie,
                 const int* __restrict__ users, const int* __restrict__ items,
                 float* __restrict__ out, int batch) {
    const int warp = (blockIdx.x * blockDim.x + threadIdx.x) >> 5;
    const int lane = threadIdx.x & 31;
    if (warp >= batch) return;

    const int u   = users[warp];
    const int it  = items[warp];
    const int itn = NUM_USERS + it;

    float4 a3 = gather_row_h<2>(u,   lane);
    float4 b3 = gather_row_h<2>(itn, lane);

    const size_t ru = (size_t)u * DIM4;
    const size_t ri = (size_t)itn * DIM4;
    float4 a0 = __ldg(reinterpret_cast<const float4*>(ue) + (size_t)u * DIM4 + lane);
    float4 a1 = __ldg(reinterpret_cast<const float4*>(g_x1) + ru + lane);
    float4 a2 = __ldg(reinterpret_cast<const float4*>(g_x2) + ru + lane);
    float4 b0 = __ldg(reinterpret_cast<const float4*>(ie) + (size_t)it * DIM4 + lane);
    float4 b1 = __ldg(reinterpret_cast<const float4*>(g_x1) + ri + lane);
    float4 b2 = __ldg(reinterpret_cast<const float4*>(g_x2) + ri + lane);

    float sux = a0.x + a1.x + a2.x + a3.x;
    float suy = a0.y + a1.y + a2.y + a3.y;
    float suz = a0.z + a1.z + a2.z + a3.z;
    float suw = a0.w + a1.w + a2.w + a3.w;

    float six = b0.x + b1.x + b2.x + b3.x;
    float siy = b0.y + b1.y + b2.y + b3.y;
    float siz = b0.z + b1.z + b2.z + b3.z;
    float siw = b0.w + b1.w + b2.w + b3.w;

    float p = sux * six + suy * siy + suz * siz + suw * siw;

    #pragma unroll
    for (int off = 16; off > 0; off >>= 1)
        p += __shfl_xor_sync(0xffffffffu, p, off);

    if (lane == 0) out[warp] = p * 0.0625f;  // mean /4 each side -> /16
}

// ---------------------------------------------------------------------------
extern "C" void kernel_launch(void* const* d_in, const int* in_sizes, int n_in,
                              void* d_out, int out_size) {
    const float* user_emb = (const float*)d_in[0];
    const float* item_emb = (const float*)d_in[1];
    const int*   src      = (const int*)  d_in[2];
    const int*   dst      = (const int*)  d_in[3];
    const float* val      = (const float*)d_in[4];
    const int*   users    = (const int*)  d_in[5];
    const int*   items    = (const int*)  d_in[6];
    float*       out      = (float*)d_out;

    const int n_edges = in_sizes[2];
    const int batch   = in_sizes[5];

    // counters+flags, bucket build (scatter also sets batch flags)
    zero_cnt_kernel<<<148, 1024>>>();
    scatter_kernel<<<(n_edges + 255) / 256, 256>>>(src, dst, val,
                                                   users, items, n_edges, batch);

    // Two pull-mode SpMM layers (one warp per dst row).
    const int spmm_blocks = (N_NODES * 32 + 255) / 256;
    spmm1_kernel<<<spmm_blocks, 256>>>(user_emb, item_emb);
    spmm2_kernel<<<spmm_blocks, 256>>>();

    // Fused layer-3 + mean + dot (one warp per batch element).
    dot_fused_kernel<<<(batch * 32 + 255) / 256, 256>>>(user_emb, item_emb,
                                                        users, items, out, batch);
}